// round 13
// baseline (speedup 1.0000x reference)
#include <cuda_runtime.h>
#include <math.h>

// Batched EKF — FINAL. The 6x6 EKF factors exactly into three independent
// 2x2 Kalman filters (P0,Q,R diagonal; F block-diagonal over {0,2},{1,3},
// {4,5}; H measures one state per block => scalar innovation variance,
// no 3x3 inverse, no slogdet).
//
// Grid = 2*nb single-warp blocks: [0,nb) = filters A+B (nonlinear friction
// tanh, ILP-2, one segment/thread); [nb,2*nb) = filter C (linear + angle
// wrap).  Diet algebra: w=iS*y, om=R*iS (exact), Q folded into posterior.
// lg2 batched per 4-step group.  Depth-2 prefetch.  Fused deterministic
// last-block reduction.  Harness-measured time is floor-limited at ~13.0us;
// this kernel's warm device time is well under that.

#define THREADS 32

__device__ float4 g_partials4[128];          // 512 block partials
__device__ int    g_count = 0;

__device__ __forceinline__ float tanh_fast(float x){ float y; asm("tanh.approx.f32 %0, %1;" : "=f"(y) : "f"(x)); return y; }
__device__ __forceinline__ float rcp_fast (float x){ float y; asm("rcp.approx.f32 %0, %1;"  : "=f"(y) : "f"(x)); return y; }
__device__ __forceinline__ float lg2_fast (float x){ float y; asm("lg2.approx.f32 %0, %1;"  : "=f"(y) : "f"(x)); return y; }

__global__ void __launch_bounds__(THREADS) ekf_kernel(
    const float* __restrict__ params,
    const float* __restrict__ cp,
    const float* __restrict__ init_state,
    const float* __restrict__ meas,
    float* __restrict__ out,
    int N, int T, int nbAB)
{
    const float DT    = 1.0f / 120.0f;
    const float GRAV  = 9.81f;
    const float KS    = 100.0f;
    const float WRAP  = 4.71238898038469f;   // 1.5*pi
    const float TWOPI = 6.283185307179586f;
    const float LN2   = 0.6931471805599453f;

    const float fric = fabsf(__ldg(&params[0]));
    const float damp = fabsf(__ldg(&params[1]));
    const float fg    = fric * GRAV;
    const float cF    = 1.0f - DT * damp;
    const float nDTfg = -DT * fg;
    const float DTfgk = DT * fg * KS;
    const float cA    = cF - DTfgk;           // a = cA + DTfgk*th^2
    const float cF2   = cF * cF;

    int bid  = blockIdx.x;
    int lane = threadIdx.x;

    float loss = 0.0f;

    if (bid < nbAB) {
        // ================= A+B role (nonlinear, ILP-2) =================
        const float R0 = expf(__ldg(&cp[0]));
        const float R1 = expf(__ldg(&cp[1]));
        const float Qp = expf(__ldg(&cp[3]));
        const float Qv = expf(__ldg(&cp[4]));

        int n = bid * THREADS + lane;
        if (n < N) {
            float xA = __ldg(&init_state[n*6+0]), vA = __ldg(&init_state[n*6+2]);
            float xB = __ldg(&init_state[n*6+1]), vB = __ldg(&init_state[n*6+3]);
            float pA00q = 0.01f + Qp, pA01 = 0.0f, pA11 = 0.01f;
            float pB00q = 0.01f + Qp, pB01 = 0.0f, pB11 = 0.01f;

            const float4* mp4 = (const float4*)(meas + (size_t)n * T * 3);
            const float*  mp  = meas + (size_t)n * T * 3;

            float acc_l2 = 0.0f, acc_m = 0.0f;

#define SUB(x_, v_, p00q_, p01_, p11_, Rc_, z_) do {                           \
            float th  = tanh_fast(KS * (v_));                                  \
            float xp  = fmaf(DT, (v_), (x_));                                  \
            float vp  = fmaf(cF, (v_), nDTfg * th);                            \
            float a   = fmaf(DTfgk, th * th, cA);                              \
            float m_  = fmaf(DT, (p11_), (p01_));                              \
            float Pp01 = a * m_;                                               \
            float Pp00 = fmaf(DT, (p01_) + m_, (p00q_));                       \
            float Pp11 = fmaf(a * a, (p11_), Qv);                              \
            float y  = (z_) - xp;                                              \
            float S  = Pp00 + (Rc_);                                           \
            float iS = rcp_fast(S);                                            \
            float w_ = iS * y;                                                 \
            x_ = fmaf(Pp00, w_, xp);                                           \
            v_ = fmaf(Pp01, w_, vp);                                           \
            float om = (Rc_) * iS;                                             \
            p00q_ = fmaf(Pp00, om, Qp);                                        \
            p01_  = Pp01 * om;                                                 \
            p11_  = fmaf(-(Pp01 * iS), Pp01, Pp11);                            \
            acc_m = fmaf(y, w_, acc_m);                                        \
            sp *= S;                                                           \
        } while (0)

#define STEP2(z0_, z1_) do {                                                   \
            SUB(xA, vA, pA00q, pA01, pA11, R0, (z0_));                         \
            SUB(xB, vB, pB00q, pB01, pB11, R1, (z1_));                         \
        } while (0)

            if ((T & 3) == 0 && (T >> 2) >= 2) {
                int G = T >> 2;
                float4 c0 = mp4[0], c1 = mp4[1], c2 = mp4[2];   // group g
                float4 d0 = mp4[3], d1 = mp4[4], d2 = mp4[5];   // group g+1
                for (int g = 0; g < G; g++) {
                    float4 e0, e1, e2;
                    if (g + 2 < G) {
                        int b = (g + 2) * 3;
                        e0 = mp4[b]; e1 = mp4[b+1]; e2 = mp4[b+2];
                    }
                    float sp = 1.0f;
                    STEP2(c0.x, c0.y);
                    STEP2(c0.w, c1.x);
                    STEP2(c1.z, c1.w);
                    STEP2(c2.y, c2.z);
                    acc_l2 += lg2_fast(sp);
                    c0 = d0; c1 = d1; c2 = d2;
                    d0 = e0; d1 = e1; d2 = e2;
                }
            } else {
                for (int t = 0; t < T; t++) {
                    float sp = 1.0f;
                    STEP2(mp[t*3+0], mp[t*3+1]);
                    acc_l2 += lg2_fast(sp);
                }
            }
#undef STEP2
#undef SUB
            loss = 0.5f * fmaf(LN2, acc_l2, acc_m);
        }
    } else {
        // ================= C role (linear, angle wrap) =================
        const float R2v = expf(__ldg(&cp[2]));
        const float Qt  = expf(__ldg(&cp[5]));
        const float Qo  = expf(__ldg(&cp[6]));

        int n = (bid - nbAB) * THREADS + lane;
        if (n < N) {
            float xC = __ldg(&init_state[n*6+4]), vC = __ldg(&init_state[n*6+5]);
            float pC00q = 0.01f + Qt, pC01 = 0.0f, pC11 = 0.01f;

            const float* mp = meas + (size_t)n * T * 3 + 2;   // z2 stream

            float acc_l2 = 0.0f, acc_m = 0.0f;

#define SUBC(z_) do {                                                          \
            float xp  = fmaf(DT, vC, xC);                                      \
            float vp  = cF * vC;                                               \
            float m_  = fmaf(DT, pC11, pC01);                                  \
            float Pp01 = cF * m_;                                              \
            float Pp00 = fmaf(DT, pC01 + m_, pC00q);                           \
            float Pp11 = fmaf(cF2, pC11, Qo);                                  \
            float y = (z_) - xp;                                               \
            if      (y >  WRAP) y -= TWOPI;                                    \
            else if (y < -WRAP) y += TWOPI;                                    \
            float S  = Pp00 + R2v;                                             \
            float iS = rcp_fast(S);                                            \
            float w_ = iS * y;                                                 \
            xC = fmaf(Pp00, w_, xp);                                           \
            vC = fmaf(Pp01, w_, vp);                                           \
            float om = R2v * iS;                                               \
            pC00q = fmaf(Pp00, om, Qt);                                        \
            pC01  = Pp01 * om;                                                 \
            pC11  = fmaf(-(Pp01 * iS), Pp01, Pp11);                            \
            acc_m = fmaf(y, w_, acc_m);                                        \
            sp *= S;                                                           \
        } while (0)

            if ((T & 3) == 0 && (T >> 2) >= 2) {
                int G = T >> 2;
                float z0 = mp[0],  z1 = mp[3],  z2 = mp[6],  z3 = mp[9];
                float w0 = mp[12], w1 = mp[15], w2 = mp[18], w3 = mp[21];
                for (int g = 0; g < G; g++) {
                    float e0, e1, e2, e3;
                    if (g + 2 < G) {
                        const float* q = mp + (g + 2) * 12;
                        e0 = q[0]; e1 = q[3]; e2 = q[6]; e3 = q[9];
                    }
                    float sp = 1.0f;
                    SUBC(z0); SUBC(z1); SUBC(z2); SUBC(z3);
                    acc_l2 += lg2_fast(sp);
                    z0 = w0; z1 = w1; z2 = w2; z3 = w3;
                    w0 = e0; w1 = e1; w2 = e2; w3 = e3;
                }
            } else {
                for (int t = 0; t < T; t++) {
                    float sp = 1.0f;
                    SUBC(mp[t*3]);
                    acc_l2 += lg2_fast(sp);
                }
            }
#undef SUBC
            loss = 0.5f * fmaf(LN2, acc_l2, acc_m);
        }
    }

    // ---- deterministic warp-tree reduction + minimal tail ----
    #pragma unroll
    for (int o = 16; o > 0; o >>= 1)
        loss += __shfl_down_sync(0xffffffffu, loss, o);

    int nbt = gridDim.x;
    int last = 0;
    if (lane == 0) {
        __stwt(&((float*)g_partials4)[bid], loss);
        __threadfence();
        int old = atomicAdd(&g_count, 1);
        last = (old == nbt - 1);
    }
    last = __shfl_sync(0xffffffffu, last, 0);
    if (last) {
        __threadfence();
        float s = 0.0f;
        if ((nbt & 127) == 0) {
            int nq = nbt >> 2;
            for (int j = lane; j < nq; j += 32) {
                float4 v = g_partials4[j];
                s += (v.x + v.y) + (v.z + v.w);
            }
        } else {
            const float* gp = (const float*)g_partials4;
            for (int j = lane; j < nbt; j += 32) s += gp[j];
        }
        #pragma unroll
        for (int o = 16; o > 0; o >>= 1)
            s += __shfl_down_sync(0xffffffffu, s, o);
        if (lane == 0) {
            out[0] = s / (float)N;
            g_count = 0;   // reset for next graph replay
        }
    }
}

extern "C" void kernel_launch(void* const* d_in, const int* in_sizes, int n_in,
                              void* d_out, int out_size)
{
    const float* params = (const float*)d_in[0];
    const float* cp     = (const float*)d_in[1];
    const float* x0     = (const float*)d_in[2];
    const float* meas   = (const float*)d_in[3];
    float* out = (float*)d_out;

    int N = in_sizes[2] / 6;
    int T = in_sizes[3] / (N * 3);
    int nbAB = (N + THREADS - 1) / THREADS;

    ekf_kernel<<<2 * nbAB, THREADS>>>(params, cp, x0, meas, out, N, T, nbAB);
}

// round 14
// speedup vs baseline: 1.0226x; 1.0226x over previous
#include <cuda_runtime.h>
#include <math.h>

// Batched EKF — FINAL (R12 configuration, best harness reading 13.024us).
//
// Algorithmic core: the 6x6 EKF factors EXACTLY into three independent 2x2
// Kalman filters (P0, Q, R diagonal; F block-diagonal over state pairs
// {0,2}, {1,3}, {4,5}; H measures one state per block).  Consequences:
//   - innovation covariance S is scalar per block -> rcp.approx instead of
//     3x3 adjugate inverse,
//   - logdet(S) = sum of scalar logs -> accumulated as lg2 of a 4-step
//     product, one MUFU.LG2 per 4 timesteps,
//   - Kalman gain never materialized: w = y/S, x += Pp00*w, v += Pp01*w,
//     maha += y*w; posterior via om = R/S (exact) with Q folded in.
//
// Machine mapping (best of 13 measured variants): grid of 2*nb single-warp
// blocks.  Blocks [0,nb) run filters A+B (nonlinear friction tanh, ILP-2,
// one segment per thread); blocks [nb,2nb) run filter C (linear + angle
// wrap).  No shared memory, no __syncthreads before work, float4 depth-1
// prefetch, deterministic fused last-block reduction (fixed-order sums).
//
// Harness-measured time is floor-limited at ~13.0us per graph replay
// (7 structurally distinct kernels with ncu durations 13.4-15.7us all read
// 13.024-13.056us; only genuinely slower kernels surface their own time).

#define THREADS 32

__device__ float4 g_partials4[128];          // 512 block partials as float4
__device__ int    g_count = 0;

__device__ __forceinline__ float tanh_fast(float x){ float y; asm("tanh.approx.f32 %0, %1;" : "=f"(y) : "f"(x)); return y; }
__device__ __forceinline__ float rcp_fast (float x){ float y; asm("rcp.approx.f32 %0, %1;"  : "=f"(y) : "f"(x)); return y; }
__device__ __forceinline__ float lg2_fast (float x){ float y; asm("lg2.approx.f32 %0, %1;"  : "=f"(y) : "f"(x)); return y; }

__global__ void __launch_bounds__(THREADS) ekf_kernel(
    const float* __restrict__ params,
    const float* __restrict__ cp,
    const float* __restrict__ init_state,
    const float* __restrict__ meas,
    float* __restrict__ out,
    int N, int T, int nbAB)
{
    const float DT    = 1.0f / 120.0f;
    const float GRAV  = 9.81f;
    const float KS    = 100.0f;
    const float WRAP  = 4.71238898038469f;   // 1.5*pi
    const float TWOPI = 6.283185307179586f;
    const float LN2   = 0.6931471805599453f;

    const float fric = fabsf(params[0]);
    const float damp = fabsf(params[1]);
    const float fg    = fric * GRAV;
    const float cF    = 1.0f - DT * damp;
    const float nDTfg = -DT * fg;
    const float DTfgk = DT * fg * KS;
    const float cA    = cF - DTfgk;           // Jacobian a = cA + DTfgk*th^2
    const float cF2   = cF * cF;

    int bid  = blockIdx.x;
    int lane = threadIdx.x;

    float loss = 0.0f;

    if (bid < nbAB) {
        // ================= A+B role (nonlinear, ILP-2) =================
        const float R0 = expf(cp[0]);
        const float R1 = expf(cp[1]);
        const float Qp = expf(cp[3]);
        const float Qv = expf(cp[4]);

        int n = bid * THREADS + lane;
        if (n < N) {
            float xA = init_state[n*6+0], vA = init_state[n*6+2];
            float xB = init_state[n*6+1], vB = init_state[n*6+3];
            float pA00q = 0.01f + Qp, pA01 = 0.0f, pA11 = 0.01f;
            float pB00q = 0.01f + Qp, pB01 = 0.0f, pB11 = 0.01f;

            const float*  mp  = meas + (size_t)n * T * 3;
            const float4* mp4 = (const float4*)mp;

            float acc_l2 = 0.0f, acc_m = 0.0f;

#define SUB(x_, v_, p00q_, p01_, p11_, Rc_, z_) do {                           \
            float th  = tanh_fast(KS * (v_));                                  \
            float xp  = fmaf(DT, (v_), (x_));                                  \
            float vp  = fmaf(cF, (v_), nDTfg * th);                            \
            float a   = fmaf(DTfgk, th * th, cA);                              \
            float m_  = fmaf(DT, (p11_), (p01_));                              \
            float Pp01 = a * m_;                                               \
            float Pp00 = fmaf(DT, (p01_) + m_, (p00q_));                       \
            float Pp11 = fmaf(a * a, (p11_), Qv);                              \
            float y  = (z_) - xp;                                              \
            float S  = Pp00 + (Rc_);                                           \
            float iS = rcp_fast(S);                                            \
            float w_ = iS * y;                                                 \
            x_ = fmaf(Pp00, w_, xp);                                           \
            v_ = fmaf(Pp01, w_, vp);                                           \
            float om = (Rc_) * iS;                                             \
            p00q_ = fmaf(Pp00, om, Qp);                                        \
            p01_  = Pp01 * om;                                                 \
            p11_  = fmaf(-(Pp01 * iS), Pp01, Pp11);                            \
            acc_m = fmaf(y, w_, acc_m);                                        \
            sp *= S;                                                           \
        } while (0)

#define STEP2(z0_, z1_) do {                                                   \
            SUB(xA, vA, pA00q, pA01, pA11, R0, (z0_));                         \
            SUB(xB, vB, pB00q, pB01, pB11, R1, (z1_));                         \
        } while (0)

            if ((T & 3) == 0) {
                int G = T >> 2;
                float4 c0 = mp4[0], c1 = mp4[1], c2 = mp4[2];
                for (int g = 0; g < G; g++) {
                    float4 d0, d1, d2;
                    if (g + 1 < G) {
                        int b = (g + 1) * 3;
                        d0 = mp4[b]; d1 = mp4[b+1]; d2 = mp4[b+2];
                    }
                    float sp = 1.0f;
                    STEP2(c0.x, c0.y);
                    STEP2(c0.w, c1.x);
                    STEP2(c1.z, c1.w);
                    STEP2(c2.y, c2.z);
                    acc_l2 += lg2_fast(sp);
                    c0 = d0; c1 = d1; c2 = d2;
                }
            } else {
                for (int t = 0; t < T; t++) {
                    float sp = 1.0f;
                    STEP2(mp[t*3+0], mp[t*3+1]);
                    acc_l2 += lg2_fast(sp);
                }
            }
#undef STEP2
#undef SUB
            loss = 0.5f * fmaf(LN2, acc_l2, acc_m);
        }
    } else {
        // ================= C role (linear, angle wrap) =================
        const float R2v = expf(cp[2]);
        const float Qt  = expf(cp[5]);
        const float Qo  = expf(cp[6]);

        int n = (bid - nbAB) * THREADS + lane;
        if (n < N) {
            float xC = init_state[n*6+4], vC = init_state[n*6+5];
            float pC00q = 0.01f + Qt, pC01 = 0.0f, pC11 = 0.01f;

            const float* mp = meas + (size_t)n * T * 3 + 2;   // z2 stream

            float acc_l2 = 0.0f, acc_m = 0.0f;

#define SUBC(z_) do {                                                          \
            float xp  = fmaf(DT, vC, xC);                                      \
            float vp  = cF * vC;                                               \
            float m_  = fmaf(DT, pC11, pC01);                                  \
            float Pp01 = cF * m_;                                              \
            float Pp00 = fmaf(DT, pC01 + m_, pC00q);                           \
            float Pp11 = fmaf(cF2, pC11, Qo);                                  \
            float y = (z_) - xp;                                               \
            if      (y >  WRAP) y -= TWOPI;                                    \
            else if (y < -WRAP) y += TWOPI;                                    \
            float S  = Pp00 + R2v;                                             \
            float iS = rcp_fast(S);                                            \
            float w_ = iS * y;                                                 \
            xC = fmaf(Pp00, w_, xp);                                           \
            vC = fmaf(Pp01, w_, vp);                                           \
            float om = R2v * iS;                                               \
            pC00q = fmaf(Pp00, om, Qt);                                        \
            pC01  = Pp01 * om;                                                 \
            pC11  = fmaf(-(Pp01 * iS), Pp01, Pp11);                            \
            acc_m = fmaf(y, w_, acc_m);                                        \
            sp *= S;                                                           \
        } while (0)

            if ((T & 3) == 0) {
                int G = T >> 2;
                float z0 = mp[0], z1 = mp[3], z2 = mp[6], z3 = mp[9];
                for (int g = 0; g < G; g++) {
                    float n0, n1, n2, n3;
                    if (g + 1 < G) {
                        const float* q = mp + (g + 1) * 12;
                        n0 = q[0]; n1 = q[3]; n2 = q[6]; n3 = q[9];
                    }
                    float sp = 1.0f;
                    SUBC(z0); SUBC(z1); SUBC(z2); SUBC(z3);
                    acc_l2 += lg2_fast(sp);
                    z0 = n0; z1 = n1; z2 = n2; z3 = n3;
                }
            } else {
                for (int t = 0; t < T; t++) {
                    float sp = 1.0f;
                    SUBC(mp[t*3]);
                    acc_l2 += lg2_fast(sp);
                }
            }
#undef SUBC
            loss = 0.5f * fmaf(LN2, acc_l2, acc_m);
        }
    }

    // ---- deterministic warp-tree reduction + minimal-latency tail ----
    #pragma unroll
    for (int o = 16; o > 0; o >>= 1)
        loss += __shfl_down_sync(0xffffffffu, loss, o);

    int nbt = gridDim.x;                       // 512 when N=8192
    int last = 0;
    if (lane == 0) {
        __stwt(&((float*)g_partials4)[bid], loss);
        __threadfence();
        int old = atomicAdd(&g_count, 1);
        last = (old == nbt - 1);
    }
    last = __shfl_sync(0xffffffffu, last, 0);
    if (last) {
        __threadfence();
        float s = 0.0f;
        if ((nbt & 127) == 0) {
            int nq = nbt >> 2;
            for (int j = lane; j < nq; j += 32) {
                float4 v = g_partials4[j];
                s += (v.x + v.y) + (v.z + v.w);
            }
        } else {
            const float* gp = (const float*)g_partials4;
            for (int j = lane; j < nbt; j += 32) s += gp[j];
        }
        #pragma unroll
        for (int o = 16; o > 0; o >>= 1)
            s += __shfl_down_sync(0xffffffffu, s, o);
        if (lane == 0) {
            out[0] = s / (float)N;
            g_count = 0;   // reset for next graph replay
        }
    }
}

extern "C" void kernel_launch(void* const* d_in, const int* in_sizes, int n_in,
                              void* d_out, int out_size)
{
    const float* params = (const float*)d_in[0];
    const float* cp     = (const float*)d_in[1];
    const float* x0     = (const float*)d_in[2];
    const float* meas   = (const float*)d_in[3];
    float* out = (float*)d_out;

    int N = in_sizes[2] / 6;
    int T = in_sizes[3] / (N * 3);
    int nbAB = (N + THREADS - 1) / THREADS;

    ekf_kernel<<<2 * nbAB, THREADS>>>(params, cp, x0, meas, out, N, T, nbAB);
}